// round 10
// baseline (speedup 1.0000x reference)
#include <cuda_runtime.h>
#include <cstdint>

#define MDIM 8192
#define KDIM 8192
#define NDIM 8192

#define ROW_TILES 148   // one row-tile per SM-resident block slot
#define COL_TILES 8     // 8 * 256 threads * float4 = 8192 columns

// ---- scratch (device globals; no allocation allowed) ----
__device__ float g_partial[ROW_TILES * KDIM]; // 4.6 MiB, overwritten each launch
__device__ float g_wcs[KDIM];                 // 32 KiB column-sum of W

// ============================================================
// Kernel 1: partial column sums of W. (stable ~41.5us, 6.5 TB/s)
// Grid: exactly COL_TILES * ROW_TILES = 1184 blocks = 8 per SM.
// Unroll 8: 8 front-batched independent LDG.128 per thread to
// maximize outstanding loads (latency hiding at DRAM tier).
// ============================================================
__global__ __launch_bounds__(256, 8) void colsum_partial(const float* __restrict__ w) {
    const int bid  = blockIdx.x;
    const int col4 = (bid & (COL_TILES - 1)) * 256 + threadIdx.x;
    const int rt   = bid >> 3;

    const float4* wp = reinterpret_cast<const float4*>(w) + col4;

    float4 acc = make_float4(0.f, 0.f, 0.f, 0.f);
    #pragma unroll 8
    for (int r = rt; r < NDIM; r += ROW_TILES) {
        float4 v = __ldcs(wp + (size_t)r * (KDIM / 4));
        acc.x += v.x; acc.y += v.y; acc.z += v.z; acc.w += v.w;
    }
    reinterpret_cast<float4*>(g_partial)[(size_t)rt * (KDIM / 4) + col4] = acc;
}

// ============================================================
// Kernel 2: fold the 148 partials -> g_wcs.
// Latency-bound: float4 coalesced loads, FULLY unrolled with
// 4 independent float4 accumulators -> 148 independent 16B
// loads per thread queued back-to-back. 8 blocks x 256 thr
// cover all 2048 float4 columns.
// ============================================================
__global__ __launch_bounds__(256) void colsum_reduce() {
    const int c4 = blockIdx.x * 256 + threadIdx.x;   // float4 column index
    const float4* p = reinterpret_cast<const float4*>(g_partial) + c4;

    float4 a0 = make_float4(0.f, 0.f, 0.f, 0.f);
    float4 a1 = a0, a2 = a0, a3 = a0;
    #pragma unroll
    for (int rt = 0; rt < ROW_TILES; rt += 4) {
        float4 v0 = p[(size_t)(rt + 0) * (KDIM / 4)];
        float4 v1 = p[(size_t)(rt + 1) * (KDIM / 4)];
        float4 v2 = p[(size_t)(rt + 2) * (KDIM / 4)];
        float4 v3 = p[(size_t)(rt + 3) * (KDIM / 4)];
        a0.x += v0.x; a0.y += v0.y; a0.z += v0.z; a0.w += v0.w;
        a1.x += v1.x; a1.y += v1.y; a1.z += v1.z; a1.w += v1.w;
        a2.x += v2.x; a2.y += v2.y; a2.z += v2.z; a2.w += v2.w;
        a3.x += v3.x; a3.y += v3.y; a3.z += v3.z; a3.w += v3.w;
    }
    float4 out;
    out.x = (a0.x + a1.x) + (a2.x + a3.x);
    out.y = (a0.y + a1.y) + (a2.y + a3.y);
    out.z = (a0.z + a1.z) + (a2.z + a3.z);
    out.w = (a0.w + a1.w) + (a2.w + a3.w);
    reinterpret_cast<float4*>(g_wcs)[c4] = out;
}

// ============================================================
// Kernel 3: y[m] = 0.75 * dot(x[m,:], wcs). Proven R2 loop:
// one 256-thread block per row, stride-256 unroll-8.
// ============================================================
__global__ __launch_bounds__(256, 8) void rowdot(const float* __restrict__ x,
                                                 float* __restrict__ y) {
    const int row = blockIdx.x;
    const int tid = threadIdx.x;
    const float4* xp = reinterpret_cast<const float4*>(x) + (size_t)row * (KDIM / 4);
    const float4* wp = reinterpret_cast<const float4*>(g_wcs);

    float4 acc = make_float4(0.f, 0.f, 0.f, 0.f);
    #pragma unroll 8
    for (int i = tid; i < KDIM / 4; i += 256) {
        float4 a = __ldcs(xp + i);   // one-touch: evict-first
        float4 b = wp[i];            // hot: stays in L2/L1
        acc.x += a.x * b.x;
        acc.y += a.y * b.y;
        acc.z += a.z * b.z;
        acc.w += a.w * b.w;
    }
    float s = (acc.x + acc.y) + (acc.z + acc.w);

    #pragma unroll
    for (int off = 16; off > 0; off >>= 1)
        s += __shfl_xor_sync(0xFFFFFFFFu, s, off);

    __shared__ float red[8];
    if ((tid & 31) == 0) red[tid >> 5] = s;
    __syncthreads();
    if (tid < 8) {
        float t = red[tid];
        #pragma unroll
        for (int off = 4; off > 0; off >>= 1)
            t += __shfl_xor_sync(0xFFu, t, off);
        if (tid == 0) y[row] = 0.75f * t;
    }
}

extern "C" void kernel_launch(void* const* d_in, const int* in_sizes, int n_in,
                              void* d_out, int out_size) {
    const float* x = (const float*)d_in[0];  // [M, K]
    const float* w = (const float*)d_in[1];  // [N, K]
    float* y = (float*)d_out;                // [M, 1]

    colsum_partial<<<COL_TILES * ROW_TILES, 256>>>(w);
    colsum_reduce<<<(KDIM / 4) / 256, 256>>>();
    rowdot<<<MDIM, 256>>>(x, y);
}

// round 12
// speedup vs baseline: 1.0853x; 1.0853x over previous
#include <cuda_runtime.h>
#include <cstdint>

#define MDIM 8192
#define KDIM 8192
#define NDIM 8192

#define ROW_TILES 148
#define COL_TILES 8
#define NBLK (ROW_TILES * COL_TILES)     // 1184 = 148 SMs * 8 blocks/SM
#define CREW 32                           // last 32 tickets do the reduce
#define CREW_START (NBLK - CREW)          // 1152

// ---- scratch (device globals; no allocation allowed) ----
__device__ float g_partial[ROW_TILES * KDIM]; // 4.6 MiB
__device__ float g_wcs[KDIM];                 // 32 KiB
__device__ unsigned g_ticket = 0;             // reset by rowdot each replay
__device__ volatile int g_flag = 0;           // reset by rowdot each replay

// ============================================================
// Kernel A: colsum_partial (proven unroll-4 loop, 41.5us) with
// fused tail-reduce. After publishing its partial, each block
// takes a ticket. The last 32 tickets form the reduce crew:
// slice = ticket-1152 -> columns [slice*256 .. slice*256+255],
// scalar full-unroll 4-accumulator sum over 148 partials (the
// R8-proven fast reduce shape). Deterministic: slice->column
// map and summation order are fixed regardless of which
// physical blocks draw which tickets.
// ============================================================
__global__ __launch_bounds__(256, 8) void colsum_fused(const float* __restrict__ w) {
    const int tid  = threadIdx.x;
    const int bid  = blockIdx.x;
    const int col4 = (bid & (COL_TILES - 1)) * 256 + tid;
    const int rt   = bid >> 3;

    // ---- streaming phase ----
    {
        const float4* wp = reinterpret_cast<const float4*>(w) + col4;
        float4 acc = make_float4(0.f, 0.f, 0.f, 0.f);
        #pragma unroll 4
        for (int r = rt; r < NDIM; r += ROW_TILES) {
            float4 v = __ldcs(wp + (size_t)r * (KDIM / 4));
            acc.x += v.x; acc.y += v.y; acc.z += v.z; acc.w += v.w;
        }
        reinterpret_cast<float4*>(g_partial)[(size_t)rt * (KDIM / 4) + col4] = acc;
    }

    // ---- publish + ticket ----
    __threadfence();              // order my partial stores before the ticket
    __syncthreads();              // all 256 threads' stores fenced
    __shared__ unsigned s_ticket;
    if (tid == 0) s_ticket = atomicAdd(&g_ticket, 1u);
    __syncthreads();
    const unsigned ticket = s_ticket;

    if (ticket < CREW_START) return;   // not in the reduce crew

    // ---- crew sync: last ticket releases; others spin briefly ----
    if (ticket == NBLK - 1) {
        // my atomicAdd returning NBLK-1 => all blocks fenced+ticketed:
        // every partial is globally visible.
        __threadfence();
        g_flag = 1;
    } else {
        if (tid == 0) {
            while (g_flag == 0) __nanosleep(64);
        }
        __syncthreads();
        __threadfence();          // acquire partials
    }

    // ---- reduce slice (R8-proven scalar full-unroll shape) ----
    {
        const int slice = (int)(ticket - CREW_START);     // 0..31
        const int k = slice * 256 + tid;                  // column
        const float* p = g_partial + k;

        float s0 = 0.f, s1 = 0.f, s2 = 0.f, s3 = 0.f;
        #pragma unroll
        for (int r = 0; r < ROW_TILES; r += 4) {
            s0 += p[(size_t)(r + 0) * KDIM];
            s1 += p[(size_t)(r + 1) * KDIM];
            s2 += p[(size_t)(r + 2) * KDIM];
            s3 += p[(size_t)(r + 3) * KDIM];
        }
        g_wcs[k] = (s0 + s1) + (s2 + s3);
    }
}

// ============================================================
// Kernel B: y[m] = 0.75 * dot(x[m,:], wcs). Proven R2 loop.
// Also resets the ticket/flag for the next graph replay
// (stream-ordered after kernel A; next replay's A sees 0s).
// ============================================================
__global__ __launch_bounds__(256, 8) void rowdot(const float* __restrict__ x,
                                                 float* __restrict__ y) {
    const int row = blockIdx.x;
    const int tid = threadIdx.x;

    if (row == 0 && tid == 0) { g_ticket = 0; g_flag = 0; }

    const float4* xp = reinterpret_cast<const float4*>(x) + (size_t)row * (KDIM / 4);
    const float4* wp = reinterpret_cast<const float4*>(g_wcs);

    float4 acc = make_float4(0.f, 0.f, 0.f, 0.f);
    #pragma unroll 8
    for (int i = tid; i < KDIM / 4; i += 256) {
        float4 a = __ldcs(xp + i);   // one-touch: evict-first
        float4 b = wp[i];            // hot: L1/L2-resident
        acc.x += a.x * b.x;
        acc.y += a.y * b.y;
        acc.z += a.z * b.z;
        acc.w += a.w * b.w;
    }
    float s = (acc.x + acc.y) + (acc.z + acc.w);

    #pragma unroll
    for (int off = 16; off > 0; off >>= 1)
        s += __shfl_xor_sync(0xFFFFFFFFu, s, off);

    __shared__ float red[8];
    if ((tid & 31) == 0) red[tid >> 5] = s;
    __syncthreads();
    if (tid < 8) {
        float t = red[tid];
        #pragma unroll
        for (int off = 4; off > 0; off >>= 1)
            t += __shfl_xor_sync(0xFFu, t, off);
        if (tid == 0) y[row] = 0.75f * t;
    }
}

extern "C" void kernel_launch(void* const* d_in, const int* in_sizes, int n_in,
                              void* d_out, int out_size) {
    const float* x = (const float*)d_in[0];  // [M, K]
    const float* w = (const float*)d_in[1];  // [N, K]
    float* y = (float*)d_out;                // [M, 1]

    colsum_fused<<<NBLK, 256>>>(w);
    rowdot<<<MDIM, 256>>>(x, y);
}

// round 13
// speedup vs baseline: 1.1341x; 1.0450x over previous
#include <cuda_runtime.h>
#include <cstdint>

#define MDIM 8192
#define KDIM 8192
#define NDIM 8192

#define ROW_TILES 148
#define COL_TILES 8
#define NBLK (ROW_TILES * COL_TILES)   // 1184 = 148 SMs * 8 blocks/SM

// ---- scratch (device globals; no allocation allowed) ----
__device__ float g_partial[ROW_TILES * KDIM]; // 4.6 MiB
__device__ float g_wcs[KDIM];                 // 32 KiB

// ============================================================
// Kernel 1: partial column sums of W (proven loop, ~41.5us).
// Triggers programmatic launch of the reduce at block end.
// ============================================================
__global__ __launch_bounds__(256, 8) void colsum_partial(const float* __restrict__ w) {
    const int bid  = blockIdx.x;
    const int col4 = (bid & (COL_TILES - 1)) * 256 + threadIdx.x;
    const int rt   = bid >> 3;

    const float4* wp = reinterpret_cast<const float4*>(w) + col4;

    float4 acc = make_float4(0.f, 0.f, 0.f, 0.f);
    #pragma unroll 4
    for (int r = rt; r < NDIM; r += ROW_TILES) {
        float4 v = __ldcs(wp + (size_t)r * (KDIM / 4));
        acc.x += v.x; acc.y += v.y; acc.z += v.z; acc.w += v.w;
    }
    reinterpret_cast<float4*>(g_partial)[(size_t)rt * (KDIM / 4) + col4] = acc;

    cudaTriggerProgrammaticLaunchCompletion();
}

// ============================================================
// Kernel 2: fold 148 partials -> g_wcs (R8-proven scalar
// full-unroll shape; latency-bound, 32 blocks). Triggers
// immediately so rowdot launches and prefetches x while this
// (and colsum's tail) still runs; griddepsync guards partials.
// ============================================================
__global__ __launch_bounds__(256) void colsum_reduce() {
    cudaTriggerProgrammaticLaunchCompletion();
    cudaGridDependencySynchronize();   // wait: colsum partials visible

    const int k = blockIdx.x * 256 + threadIdx.x;
    const float* p = g_partial + k;

    float s0 = 0.f, s1 = 0.f, s2 = 0.f, s3 = 0.f;
    #pragma unroll
    for (int rt = 0; rt < ROW_TILES; rt += 4) {
        s0 += p[(size_t)(rt + 0) * KDIM];
        s1 += p[(size_t)(rt + 1) * KDIM];
        s2 += p[(size_t)(rt + 2) * KDIM];
        s3 += p[(size_t)(rt + 3) * KDIM];
    }
    g_wcs[k] = (s0 + s1) + (s2 + s3);
}

// ============================================================
// Kernel 3: y[m] = 0.75 * dot(x[m,:], wcs). Proven R2 shape,
// restructured for PDL: the thread's ENTIRE x slice (8
// independent LDG.128, wcs-independent) is prefetched BEFORE
// cudaGridDependencySynchronize, hiding the reduce kernel +
// launch gaps behind x streaming.
// ============================================================
__global__ __launch_bounds__(256) void rowdot(const float* __restrict__ x,
                                              float* __restrict__ y) {
    const int row = blockIdx.x;
    const int tid = threadIdx.x;
    const float4* xp = reinterpret_cast<const float4*>(x) + (size_t)row * (KDIM / 4);

    // prefetch x slice (independent of wcs)
    float4 a[8];
    #pragma unroll
    for (int j = 0; j < 8; ++j)
        a[j] = __ldcs(xp + tid + 256 * j);

    cudaGridDependencySynchronize();   // wait: g_wcs ready

    const float4* wp = reinterpret_cast<const float4*>(g_wcs);
    float s = 0.f;
    #pragma unroll
    for (int j = 0; j < 8; ++j) {
        float4 b = wp[tid + 256 * j];
        s += a[j].x * b.x + a[j].y * b.y + a[j].z * b.z + a[j].w * b.w;
    }

    #pragma unroll
    for (int off = 16; off > 0; off >>= 1)
        s += __shfl_xor_sync(0xFFFFFFFFu, s, off);

    __shared__ float red[8];
    if ((tid & 31) == 0) red[tid >> 5] = s;
    __syncthreads();
    if (tid < 8) {
        float t = red[tid];
        #pragma unroll
        for (int off = 4; off > 0; off >>= 1)
            t += __shfl_xor_sync(0xFFu, t, off);
        if (tid == 0) y[row] = 0.75f * t;
    }
}

extern "C" void kernel_launch(void* const* d_in, const int* in_sizes, int n_in,
                              void* d_out, int out_size) {
    const float* x = (const float*)d_in[0];  // [M, K]
    const float* w = (const float*)d_in[1];  // [N, K]
    float* y = (float*)d_out;                // [M, 1]

    // k1: normal launch
    colsum_partial<<<NBLK, 256>>>(w);

    // k2, k3: programmatic dependent launches (overlap with predecessor)
    cudaLaunchAttribute pdl;
    pdl.id = cudaLaunchAttributeProgrammaticStreamSerialization;
    pdl.val.programmaticStreamSerializationAllowed = 1;

    {
        cudaLaunchConfig_t cfg = {};
        cfg.gridDim = dim3(KDIM / 256);
        cfg.blockDim = dim3(256);
        cfg.attrs = &pdl;
        cfg.numAttrs = 1;
        cudaLaunchKernelEx(&cfg, colsum_reduce);
    }
    {
        cudaLaunchConfig_t cfg = {};
        cfg.gridDim = dim3(MDIM);
        cfg.blockDim = dim3(256);
        cfg.attrs = &pdl;
        cfg.numAttrs = 1;
        cudaLaunchKernelEx(&cfg, rowdot, x, y);
    }
}